// round 1
// baseline (speedup 1.0000x reference)
#include <cuda_runtime.h>
#include <stdint.h>

// Problem constants
#define X_COORD_START 10
#define Y_COORD_START 21
#define EOS_TOKEN     39
#define MAX_REACH     5.0f
#define WINDOW_SIZE   4
#define PENALTY_SCALE 1.0f

#define ROW_LEN 2048          // tokens per row
#define HPAIRS  1023          // number of (x,y) pairs per row: indices 2..2047

// Scratch accumulators (no device allocation allowed)
__device__ double g_total;
__device__ int    g_nvs;

__global__ void zero_accum_kernel() {
    g_total = 0.0;
    g_nvs = 0;
}

__global__ __launch_bounds__(1024, 2)
void reach_loss_main(const int* __restrict__ in) {
    const int row  = blockIdx.x;
    const int t    = threadIdx.x;
    const int lane = t & 31;
    const int wid  = t >> 5;

    __shared__ float sx[HPAIRS];
    __shared__ float sy[HPAIRS];
    __shared__ int   warp_sums[32];
    __shared__ float warp_red[32];
    __shared__ int   s_count;

    // ---- Load pair t: x = row[2+2t], y = row[3+2t] (coalesced int2) ----
    int x = 0, y = 0;
    bool valid = false;
    if (t < HPAIRS) {
        const int2 p = reinterpret_cast<const int2*>(in + (size_t)row * ROW_LEN + 2)[t];
        x = p.x; y = p.y;
        valid = (x >= X_COORD_START) & (x < Y_COORD_START) &
                (y >= Y_COORD_START) & (y < EOS_TOKEN);
    }

    // ---- Stable stream compaction: block-wide exclusive scan of valid flags ----
    int f = valid ? 1 : 0;
    int inc = f;
    #pragma unroll
    for (int o = 1; o < 32; o <<= 1) {
        int v = __shfl_up_sync(0xffffffffu, inc, o);
        if (lane >= o) inc += v;
    }
    if (lane == 31) warp_sums[wid] = inc;
    __syncthreads();
    if (wid == 0) {
        int s = warp_sums[lane];
        #pragma unroll
        for (int o = 1; o < 32; o <<= 1) {
            int v = __shfl_up_sync(0xffffffffu, s, o);
            if (lane >= o) s += v;
        }
        warp_sums[lane] = s;
        if (lane == 31) s_count = s;
    }
    __syncthreads();
    const int base = (wid > 0) ? warp_sums[wid - 1] : 0;
    const int pos  = base + inc - f;   // exclusive position
    if (valid) {
        sx[pos] = (float)(x - X_COORD_START);
        sy[pos] = (float)(y - Y_COORD_START + 1);
    }
    __syncthreads();
    const int count = s_count;

    // ---- Windowed min-distance violation per check position ----
    float viol = 0.0f;
    if (t >= WINDOW_SIZE && t < HPAIRS && t < count) {
        const float xi = sx[t];
        const float yi = sy[t];
        float mind = 3.402823466e+38f;
        #pragma unroll
        for (int j = 1; j <= WINDOW_SIZE; j++) {
            const float dx = xi - sx[t - j];
            const float dy = yi - sy[t - j];
            const float d  = sqrtf(dx * dx + dy * dy);
            mind = fminf(mind, d);
        }
        viol = fmaxf(mind - MAX_REACH, 0.0f);
    }

    // ---- Block reduction of viol ----
    #pragma unroll
    for (int o = 16; o > 0; o >>= 1)
        viol += __shfl_xor_sync(0xffffffffu, viol, o);
    if (lane == 0) warp_red[wid] = viol;
    __syncthreads();
    if (t == 0) {
        float seq_pen = 0.0f;
        #pragma unroll
        for (int w = 0; w < 32; w++) seq_pen += warp_red[w];
        if (count >= WINDOW_SIZE + 1) {
            const int num_checks = (count - WINDOW_SIZE) > 1 ? (count - WINDOW_SIZE) : 1;
            atomicAdd(&g_total, (double)(seq_pen / (float)num_checks));
            atomicAdd(&g_nvs, 1);
        }
    }
}

__global__ void finalize_kernel(float* __restrict__ out) {
    const double total = g_total;
    const int nvs = g_nvs;
    out[0] = (nvs > 0) ? (float)(PENALTY_SCALE * total / (double)nvs) : 0.0f;
}

extern "C" void kernel_launch(void* const* d_in, const int* in_sizes, int n_in,
                              void* d_out, int out_size) {
    const int* in = (const int*)d_in[0];
    const int B = in_sizes[0] / ROW_LEN;
    float* out = (float*)d_out;

    zero_accum_kernel<<<1, 1>>>();
    reach_loss_main<<<B, 1024>>>(in);
    finalize_kernel<<<1, 1>>>(out);
}

// round 2
// speedup vs baseline: 1.2763x; 1.2763x over previous
#include <cuda_runtime.h>
#include <stdint.h>

#define X_COORD_START 10
#define Y_COORD_START 21
#define EOS_TOKEN     39
#define MAX_REACH     5.0f
#define WINDOW_SIZE   4
#define PENALTY_SCALE 1.0f

#define ROW_LEN 2048     // tokens per row
#define HPAIRS  1023     // pairs per row: token indices (2,3),(4,5),...,(2046,2047)
#define NTHREADS 512

// Self-resetting scratch (zero-initialized at module load; last block resets
// after every launch so each graph replay starts from zero — deterministic).
__device__ double        g_total   = 0.0;
__device__ int           g_nvs     = 0;
__device__ unsigned int  g_counter = 0;

__device__ __forceinline__ bool is_valid(int x, int y) {
    return (x >= X_COORD_START) & (x < Y_COORD_START) &
           (y >= Y_COORD_START) & (y < EOS_TOKEN);
}

__global__ __launch_bounds__(NTHREADS, 4)
void reach_loss_fused(const int* __restrict__ in, float* __restrict__ out,
                      int n_rows) {
    const int row  = blockIdx.x;
    const int t    = threadIdx.x;
    const int lane = t & 31;
    const int wid  = t >> 5;   // 0..15

    __shared__ float sx[HPAIRS + 1];
    __shared__ float sy[HPAIRS + 1];
    __shared__ int   warp_sums[16];
    __shared__ float warp_red[16];
    __shared__ int   s_count;

    // ---- Load: thread t reads aligned int4 covering tokens 4t..4t+3 ----
    // pair A = index 2t-1 = tokens (4t, 4t+1)   [only for t >= 1]
    // pair B = index 2t   = tokens (4t+2, 4t+3) [always, max index 1022]
    const int4 p = reinterpret_cast<const int4*>(in + (size_t)row * ROW_LEN)[t];
    const bool va = (t >= 1) && is_valid(p.x, p.y);
    const bool vb = is_valid(p.z, p.w);
    const int fa = va ? 1 : 0;
    const int fb = vb ? 1 : 0;
    const int tsum = fa + fb;

    // ---- Block exclusive scan of per-thread sums (stable compaction) ----
    int inc = tsum;
    #pragma unroll
    for (int o = 1; o < 32; o <<= 1) {
        int v = __shfl_up_sync(0xffffffffu, inc, o);
        if (lane >= o) inc += v;
    }
    if (lane == 31) warp_sums[wid] = inc;
    __syncthreads();
    if (wid == 0 && lane < 16) {
        int s = warp_sums[lane];
        #pragma unroll
        for (int o = 1; o < 16; o <<= 1) {
            int v = __shfl_up_sync(0x0000ffffu, s, o);
            if (lane >= o) s += v;
        }
        warp_sums[lane] = s;
        if (lane == 15) s_count = s;
    }
    __syncthreads();
    const int warp_base = (wid > 0) ? warp_sums[wid - 1] : 0;
    const int base = warp_base + inc - tsum;   // exclusive position of pair A
    if (va) {
        sx[base] = (float)(p.x - X_COORD_START);
        sy[base] = (float)(p.y - Y_COORD_START + 1);
    }
    if (vb) {
        sx[base + fa] = (float)(p.z - X_COORD_START);
        sy[base + fa] = (float)(p.w - Y_COORD_START + 1);
    }
    __syncthreads();
    const int count = s_count;

    // ---- Windowed min-distance violations over compacted coords ----
    float vsum = 0.0f;
    for (int i = WINDOW_SIZE + t; i < count; i += NTHREADS) {
        const float xi = sx[i];
        const float yi = sy[i];
        float mind = 3.402823466e+38f;
        #pragma unroll
        for (int j = 1; j <= WINDOW_SIZE; j++) {
            const float dx = xi - sx[i - j];
            const float dy = yi - sy[i - j];
            mind = fminf(mind, sqrtf(dx * dx + dy * dy));
        }
        vsum += fmaxf(mind - MAX_REACH, 0.0f);
    }

    // ---- Block reduction ----
    #pragma unroll
    for (int o = 16; o > 0; o >>= 1)
        vsum += __shfl_xor_sync(0xffffffffu, vsum, o);
    if (lane == 0) warp_red[wid] = vsum;
    __syncthreads();

    if (t == 0) {
        float seq_pen = 0.0f;
        #pragma unroll
        for (int w = 0; w < 16; w++) seq_pen += warp_red[w];
        if (count >= WINDOW_SIZE + 1) {
            const int nc = count - WINDOW_SIZE;
            const int num_checks = nc > 1 ? nc : 1;
            atomicAdd(&g_total, (double)(seq_pen / (float)num_checks));
            atomicAdd(&g_nvs, 1);
        }
        // Last-block-done: finalize + reset scratch for the next replay.
        __threadfence();
        const unsigned ticket = atomicAdd(&g_counter, 1u);
        if (ticket == (unsigned)(n_rows - 1)) {
            const double total = *((volatile double*)&g_total);
            const int    nvs   = *((volatile int*)&g_nvs);
            out[0] = (nvs > 0) ? (float)(PENALTY_SCALE * total / (double)nvs)
                               : 0.0f;
            g_total   = 0.0;
            g_nvs     = 0;
            __threadfence();
            g_counter = 0u;
        }
    }
}

extern "C" void kernel_launch(void* const* d_in, const int* in_sizes, int n_in,
                              void* d_out, int out_size) {
    const int* in = (const int*)d_in[0];
    const int B = in_sizes[0] / ROW_LEN;
    reach_loss_fused<<<B, NTHREADS>>>(in, (float*)d_out, B);
}

// round 3
// speedup vs baseline: 1.4354x; 1.1247x over previous
#include <cuda_runtime.h>
#include <stdint.h>

#define X_COORD_START 10
#define Y_COORD_START 21
#define EOS_TOKEN     39
#define MAX_REACH     5.0f
#define WINDOW_SIZE   4
#define PENALTY_SCALE 1.0f

#define ROW_LEN      2048   // tokens per row
#define HPAIRS       1023   // pairs per row
#define NTHREADS     512
#define ROWS_PER_CTA 4

// Self-resetting scratch (zero at module load; last CTA resets after each
// launch so every graph replay starts from zero — deterministic).
__device__ double        g_total   = 0.0;
__device__ int           g_nvs     = 0;
__device__ unsigned int  g_counter = 0;

__device__ __forceinline__ bool is_valid(int x, int y) {
    return (x >= X_COORD_START) & (x < Y_COORD_START) &
           (y >= Y_COORD_START) & (y < EOS_TOKEN);
}

__global__ __launch_bounds__(NTHREADS, 4)
void reach_loss_pipe(const int* __restrict__ in, float* __restrict__ out,
                     int n_ctas) {
    const int t    = threadIdx.x;
    const int lane = t & 31;
    const int wid  = t >> 5;   // 0..15

    __shared__ float2 sxy[HPAIRS];
    __shared__ int    warp_sums[16];
    __shared__ float  warp_red[16];
    __shared__ int    s_count;

    const int row0 = blockIdx.x * ROWS_PER_CTA;

    // Prologue: load first row's int4 (tokens 4t..4t+3)
    int4 p_next = reinterpret_cast<const int4*>(in + (size_t)row0 * ROW_LEN)[t];

    double acc = 0.0;   // only meaningful on thread 0
    int    nvs = 0;

    #pragma unroll 1
    for (int r = 0; r < ROWS_PER_CTA; r++) {
        const int4 p = p_next;
        // Issue next row's load NOW — its latency hides under this row's
        // scan barriers and window compute.
        if (r + 1 < ROWS_PER_CTA)
            p_next = reinterpret_cast<const int4*>(
                         in + (size_t)(row0 + r + 1) * ROW_LEN)[t];

        // pair A = compacted-source index 2t-1 (tokens 4t,4t+1), t>=1 only
        // pair B = index 2t (tokens 4t+2,4t+3)
        const bool va = (t >= 1) && is_valid(p.x, p.y);
        const bool vb = is_valid(p.z, p.w);
        const int fa = va ? 1 : 0;
        const int tsum = fa + (vb ? 1 : 0);

        // Block exclusive scan of per-thread valid counts (stable compaction)
        int inc = tsum;
        #pragma unroll
        for (int o = 1; o < 32; o <<= 1) {
            int v = __shfl_up_sync(0xffffffffu, inc, o);
            if (lane >= o) inc += v;
        }
        if (lane == 31) warp_sums[wid] = inc;
        __syncthreads();
        if (wid == 0 && lane < 16) {
            int s = warp_sums[lane];
            #pragma unroll
            for (int o = 1; o < 16; o <<= 1) {
                int v = __shfl_up_sync(0x0000ffffu, s, o);
                if (lane >= o) s += v;
            }
            warp_sums[lane] = s;
            if (lane == 15) s_count = s;
        }
        __syncthreads();
        const int base = ((wid > 0) ? warp_sums[wid - 1] : 0) + inc - tsum;
        if (va)
            sxy[base] = make_float2((float)(p.x - X_COORD_START),
                                    (float)(p.y - Y_COORD_START + 1));
        if (vb)
            sxy[base + fa] = make_float2((float)(p.z - X_COORD_START),
                                         (float)(p.w - Y_COORD_START + 1));
        __syncthreads();
        const int count = s_count;

        // Windowed min-distance violations (count ~ 133, single pass)
        float vsum = 0.0f;
        for (int i = WINDOW_SIZE + t; i < count; i += NTHREADS) {
            const float2 ci = sxy[i];
            float mind = 3.402823466e+38f;
            #pragma unroll
            for (int j = 1; j <= WINDOW_SIZE; j++) {
                const float2 cj = sxy[i - j];
                const float dx = ci.x - cj.x;
                const float dy = ci.y - cj.y;
                mind = fminf(mind, sqrtf(dx * dx + dy * dy));
            }
            vsum += fmaxf(mind - MAX_REACH, 0.0f);
        }

        // Block reduction
        #pragma unroll
        for (int o = 16; o > 0; o >>= 1)
            vsum += __shfl_xor_sync(0xffffffffu, vsum, o);
        if (lane == 0) warp_red[wid] = vsum;
        __syncthreads();

        if (t == 0 && count >= WINDOW_SIZE + 1) {
            float seq_pen = 0.0f;
            #pragma unroll
            for (int w = 0; w < 16; w++) seq_pen += warp_red[w];
            const int nc = count - WINDOW_SIZE;
            acc += (double)(seq_pen / (float)(nc > 1 ? nc : 1));
            nvs += 1;
        }
        __syncthreads();   // protect warp_red/sxy reuse next iteration
    }

    // One global accumulation per CTA; last CTA finalizes + resets scratch.
    if (t == 0) {
        if (nvs > 0) {
            atomicAdd(&g_total, acc);
            atomicAdd(&g_nvs, nvs);
        }
        __threadfence();
        const unsigned ticket = atomicAdd(&g_counter, 1u);
        if (ticket == (unsigned)(n_ctas - 1)) {
            const double total = *((volatile double*)&g_total);
            const int    tnvs  = *((volatile int*)&g_nvs);
            out[0] = (tnvs > 0) ? (float)(PENALTY_SCALE * total / (double)tnvs)
                                : 0.0f;
            g_total = 0.0;
            g_nvs   = 0;
            __threadfence();
            g_counter = 0u;
        }
    }
}

extern "C" void kernel_launch(void* const* d_in, const int* in_sizes, int n_in,
                              void* d_out, int out_size) {
    const int* in = (const int*)d_in[0];
    const int B = in_sizes[0] / ROW_LEN;          // 2048
    const int n_ctas = B / ROWS_PER_CTA;          // 512
    reach_loss_pipe<<<n_ctas, NTHREADS>>>(in, (float*)d_out, n_ctas);
}

// round 4
// speedup vs baseline: 1.8479x; 1.2873x over previous
#include <cuda_runtime.h>
#include <stdint.h>

#define X_COORD_START 10
#define Y_COORD_START 21
#define EOS_TOKEN     39
#define MAX_REACH     5.0f
#define WINDOW_SIZE   4
#define PENALTY_SCALE 1.0f

#define ROW_LEN      2048   // tokens per row
#define NW           4      // warps (= rows) per CTA
#define NTHREADS     (NW * 32)
#define NCHUNKS      16     // 16 chunks x 32 lanes x int4 = 2048 tokens

// Self-resetting scratch (zero at module load; last CTA resets after each
// launch so every graph replay starts from zero — deterministic).
__device__ double        g_total   = 0.0;
__device__ int           g_nvs     = 0;
__device__ unsigned int  g_counter = 0;

__device__ __forceinline__ bool is_valid(int x, int y) {
    return ((unsigned)(x - X_COORD_START) < (unsigned)(Y_COORD_START - X_COORD_START)) &
           ((unsigned)(y - Y_COORD_START) < (unsigned)(EOS_TOKEN - Y_COORD_START));
}

__global__ __launch_bounds__(NTHREADS, 8)
void reach_loss_warp(const int* __restrict__ in, float* __restrict__ out,
                     int n_ctas) {
    const int t    = threadIdx.x;
    const int lane = t & 31;
    const int wid  = t >> 5;          // 0..NW-1 : warp = row
    const unsigned lt = (1u << lane) - 1u;

    __shared__ int   sw[NW][1024];    // compacted packed coords per warp/row
    __shared__ float red[NW];
    __shared__ int   redn[NW];

    const int row = blockIdx.x * NW + wid;
    const int* rowp = in + (size_t)row * ROW_LEN;

    // ---- Preload the whole row: 16 independent LDG.128 (MLP=16) ----
    int4 v[NCHUNKS];
    #pragma unroll
    for (int c = 0; c < NCHUNKS; c++)
        v[c] = reinterpret_cast<const int4*>(rowp)[c * 32 + lane];

    // ---- Warp-ballot stable compaction into warp-private smem ----
    // int4 q (q = c*32+lane) holds pair A = 2q-1 (tokens 4q,4q+1; q>=1 only)
    // and pair B = 2q (tokens 4q+2,4q+3). Pair order == (lane, A then B) order.
    int cnt = 0;
    #pragma unroll
    for (int c = 0; c < NCHUNKS; c++) {
        const int4 p = v[c];
        const bool va = ((c | lane) != 0) && is_valid(p.x, p.y);
        const bool vb = is_valid(p.z, p.w);
        const unsigned bA = __ballot_sync(0xffffffffu, va);
        const unsigned bB = __ballot_sync(0xffffffffu, vb);
        const int pos = cnt + __popc(bA & lt) + __popc(bB & lt);
        if (va) sw[wid][pos]            = (p.y << 16) | p.x;
        if (vb) sw[wid][pos + (va?1:0)] = (p.w << 16) | p.z;
        cnt += __popc(bA) + __popc(bB);
    }
    __syncwarp();

    // ---- Windowed min squared distance (integer), one sqrt per element ----
    float vsum = 0.0f;
    for (int i = WINDOW_SIZE + lane; i < cnt; i += 32) {
        const int pki = sw[wid][i];
        const int xi = pki & 0xffff;
        const int yi = pki >> 16;
        int msq = 0x7fffffff;
        #pragma unroll
        for (int j = 1; j <= WINDOW_SIZE; j++) {
            const int pkj = sw[wid][i - j];
            const int dx = xi - (pkj & 0xffff);
            const int dy = yi - (pkj >> 16);
            msq = min(msq, dx * dx + dy * dy);
        }
        // viol = max(sqrt(msq) - 5, 0); exact for msq<=25 (incl. 0) -> 0
        vsum += fmaxf(sqrtf((float)msq) - MAX_REACH, 0.0f);
    }

    // ---- Warp reduce, per-row normalize ----
    #pragma unroll
    for (int o = 16; o > 0; o >>= 1)
        vsum += __shfl_xor_sync(0xffffffffu, vsum, o);
    if (lane == 0) {
        const bool sv = cnt >= WINDOW_SIZE + 1;
        red[wid]  = sv ? vsum / (float)(cnt - WINDOW_SIZE) : 0.0f;
        redn[wid] = sv ? 1 : 0;
    }
    __syncthreads();

    // ---- One atomic pair per CTA; last CTA finalizes + resets ----
    if (t == 0) {
        double a = 0.0; int n = 0;
        #pragma unroll
        for (int w = 0; w < NW; w++) { a += (double)red[w]; n += redn[w]; }
        if (n) {
            atomicAdd(&g_total, a);
            atomicAdd(&g_nvs, n);
        }
        __threadfence();
        const unsigned ticket = atomicAdd(&g_counter, 1u);
        if (ticket == (unsigned)(n_ctas - 1)) {
            const double total = *((volatile double*)&g_total);
            const int    tnvs  = *((volatile int*)&g_nvs);
            out[0] = (tnvs > 0) ? (float)(PENALTY_SCALE * total / (double)tnvs)
                                : 0.0f;
            g_total = 0.0;
            g_nvs   = 0;
            __threadfence();
            g_counter = 0u;
        }
    }
}

extern "C" void kernel_launch(void* const* d_in, const int* in_sizes, int n_in,
                              void* d_out, int out_size) {
    const int* in = (const int*)d_in[0];
    const int B = in_sizes[0] / ROW_LEN;      // 2048 rows
    const int n_ctas = B / NW;                // 512
    reach_loss_warp<<<n_ctas, NTHREADS>>>(in, (float*)d_out, n_ctas);
}

// round 5
// speedup vs baseline: 1.9181x; 1.0380x over previous
#include <cuda_runtime.h>
#include <stdint.h>

#define X_COORD_START 10
#define Y_COORD_START 21
#define EOS_TOKEN     39
#define MAX_REACH     5.0f
#define WINDOW_SIZE   4
#define PENALTY_SCALE 1.0f

#define ROW_LEN      2048   // tokens per row
#define ROWS_PER_CTA 4
#define NTHREADS     256    // 8 warps: 2 warps per row
#define HCHUNKS      8      // chunks per half-row (8 x 32 lanes x int4 = 1024 tokens)
#define SEG          512    // max compacted pairs per half-row

// Self-resetting scratch (zero at module load; last CTA resets after each
// launch so every graph replay starts from zero — deterministic).
__device__ double        g_total   = 0.0;
__device__ int           g_nvs     = 0;
__device__ unsigned int  g_counter = 0;

__device__ __forceinline__ bool is_valid(int x, int y) {
    return ((unsigned)(x - X_COORD_START) < (unsigned)(Y_COORD_START - X_COORD_START)) &
           ((unsigned)(y - Y_COORD_START) < (unsigned)(EOS_TOKEN - Y_COORD_START));
}

__global__ __launch_bounds__(NTHREADS, 4)
void reach_loss_half(const int* __restrict__ in, float* __restrict__ out,
                     int n_ctas) {
    const int t    = threadIdx.x;
    const int lane = t & 31;
    const int wid  = t >> 5;          // 0..7
    const int r    = wid >> 1;        // row within CTA: 0..3
    const int half = wid & 1;         // 0 = first half, 1 = second half
    const unsigned lt = (1u << lane) - 1u;

    __shared__ int   sw[ROWS_PER_CTA][2][SEG];  // compacted packed coords
    __shared__ int   scnt[ROWS_PER_CTA][2];
    __shared__ float partial[8];

    const int row = blockIdx.x * ROWS_PER_CTA + r;
    const int* rowp = in + (size_t)row * ROW_LEN;

    // ---- Preload this half-row: 8 independent LDG.128 (MLP=8) ----
    int4 v[HCHUNKS];
    #pragma unroll
    for (int c = 0; c < HCHUNKS; c++)
        v[c] = reinterpret_cast<const int4*>(rowp)[(half * HCHUNKS + c) * 32 + lane];

    // ---- Warp-ballot stable compaction into this half's smem segment ----
    // Global int4 q = (half*8+c)*32+lane holds pair A = 2q-1 (tokens 4q,4q+1;
    // q>=1 only) and pair B = 2q (tokens 4q+2,4q+3).
    int cnt = 0;
    #pragma unroll
    for (int c = 0; c < HCHUNKS; c++) {
        const int4 p = v[c];
        const int g = half * HCHUNKS + c;
        const bool va = ((g | lane) != 0) && is_valid(p.x, p.y);
        const bool vb = is_valid(p.z, p.w);
        const unsigned bA = __ballot_sync(0xffffffffu, va);
        const unsigned bB = __ballot_sync(0xffffffffu, vb);
        const int pos = cnt + __popc(bA & lt) + __popc(bB & lt);
        if (va) sw[r][half][pos]              = (p.y << 16) | p.x;
        if (vb) sw[r][half][pos + (va ? 1 : 0)] = (p.w << 16) | p.z;
        cnt += __popc(bA) + __popc(bB);
    }
    if (lane == 0) scnt[r][half] = cnt;
    __syncthreads();

    const int cntA  = scnt[r][0];
    const int total = cntA + scnt[r][1];

    // ---- Windowed min squared distance over logical concat(segA, segB) ----
    const int* segA = sw[r][0];
    const int* segB = sw[r][1] - cntA;   // segB[i] valid for i >= cntA
    float vsum = 0.0f;
    for (int i = WINDOW_SIZE + lane + 32 * half; i < total; i += 64) {
        const int pki = (i < cntA) ? segA[i] : segB[i];
        const int xi = pki & 0xffff;
        const int yi = pki >> 16;
        int msq = 0x7fffffff;
        #pragma unroll
        for (int j = 1; j <= WINDOW_SIZE; j++) {
            const int k = i - j;
            const int pkj = (k < cntA) ? segA[k] : segB[k];
            const int dx = xi - (pkj & 0xffff);
            const int dy = yi - (pkj >> 16);
            msq = min(msq, dx * dx + dy * dy);
        }
        // viol = max(sqrt(msq) - 5, 0); exact 0 for msq <= 25 (incl. msq==0)
        vsum += fmaxf(sqrtf((float)msq) - MAX_REACH, 0.0f);
    }

    #pragma unroll
    for (int o = 16; o > 0; o >>= 1)
        vsum += __shfl_xor_sync(0xffffffffu, vsum, o);
    if (lane == 0) partial[wid] = vsum;
    __syncthreads();

    // ---- One atomic pair per CTA; last CTA finalizes + resets ----
    if (t == 0) {
        double a = 0.0; int n = 0;
        #pragma unroll
        for (int rr = 0; rr < ROWS_PER_CTA; rr++) {
            const int c = scnt[rr][0] + scnt[rr][1];
            if (c >= WINDOW_SIZE + 1) {
                const float pen = partial[2 * rr] + partial[2 * rr + 1];
                a += (double)(pen / (float)(c - WINDOW_SIZE));
                n += 1;
            }
        }
        if (n) {
            atomicAdd(&g_total, a);
            atomicAdd(&g_nvs, n);
        }
        __threadfence();
        const unsigned ticket = atomicAdd(&g_counter, 1u);
        if (ticket == (unsigned)(n_ctas - 1)) {
            const double tot = *((volatile double*)&g_total);
            const int    tn  = *((volatile int*)&g_nvs);
            out[0] = (tn > 0) ? (float)(PENALTY_SCALE * tot / (double)tn) : 0.0f;
            g_total = 0.0;
            g_nvs   = 0;
            __threadfence();
            g_counter = 0u;
        }
    }
}

extern "C" void kernel_launch(void* const* d_in, const int* in_sizes, int n_in,
                              void* d_out, int out_size) {
    const int* in = (const int*)d_in[0];
    const int B = in_sizes[0] / ROW_LEN;            // 2048 rows
    const int n_ctas = B / ROWS_PER_CTA;            // 512
    reach_loss_half<<<n_ctas, NTHREADS>>>(in, (float*)d_out, n_ctas);
}

// round 6
// speedup vs baseline: 1.9351x; 1.0088x over previous
#include <cuda_runtime.h>
#include <stdint.h>

#define X_COORD_START 10
#define Y_COORD_START 21
#define EOS_TOKEN     39
#define MAX_REACH     5.0f
#define WINDOW_SIZE   4
#define PENALTY_SCALE 1.0f

#define ROW_LEN      2048   // tokens per row
#define ROWS_PER_CTA 2
#define NW           4      // warps per CTA (all 4 cooperate on one row)
#define NTHREADS     128
#define WCHUNKS      4      // int4 chunks per warp (4 warps x 4 x 32 x int4 = 2048 tokens)

// Self-resetting scratch (zero at module load; last CTA resets after each
// launch so every graph replay starts from zero — deterministic).
__device__ double        g_total   = 0.0;
__device__ int           g_nvs     = 0;
__device__ unsigned int  g_counter = 0;

__device__ __forceinline__ bool is_valid(int x, int y) {
    return ((unsigned)(x - X_COORD_START) < (unsigned)(Y_COORD_START - X_COORD_START)) &
           ((unsigned)(y - Y_COORD_START) < (unsigned)(EOS_TOKEN - Y_COORD_START));
}

__global__ __launch_bounds__(NTHREADS, 7)
void reach_loss_wave(const int* __restrict__ in, float* __restrict__ out,
                     int n_ctas) {
    const int t    = threadIdx.x;
    const int lane = t & 31;
    const int wid  = t >> 5;          // 0..3
    const unsigned lt = (1u << lane) - 1u;

    __shared__ int   buf[1024];       // contiguous compacted packed coords
    __shared__ int   scnt[NW];
    __shared__ float partial[NW];

    const int row0 = blockIdx.x * ROWS_PER_CTA;

    // Prologue: preload row 0 (warp w covers int4 indices (w*4+c)*32+lane)
    int4 v[WCHUNKS], vn[WCHUNKS];
    #pragma unroll
    for (int c = 0; c < WCHUNKS; c++)
        v[c] = reinterpret_cast<const int4*>(in + (size_t)row0 * ROW_LEN)
                   [(wid * WCHUNKS + c) * 32 + lane];

    double acc = 0.0;   // thread 0 only
    int    nvs = 0;

    #pragma unroll
    for (int r = 0; r < ROWS_PER_CTA; r++) {
        // Issue next row's loads now — latency hides under this row's work.
        if (r + 1 < ROWS_PER_CTA) {
            #pragma unroll
            for (int c = 0; c < WCHUNKS; c++)
                vn[c] = reinterpret_cast<const int4*>(
                            in + (size_t)(row0 + r + 1) * ROW_LEN)
                            [(wid * WCHUNKS + c) * 32 + lane];
        }

        // ---- Pass 1: ballots + per-warp count (ballots kept in regs) ----
        // int4 q = (wid*4+c)*32+lane holds pair A = 2q-1 (tokens 4q,4q+1;
        // q>=1 only) and pair B = 2q (tokens 4q+2,4q+3).
        unsigned bA[WCHUNKS], bB[WCHUNKS];
        int cntc[WCHUNKS];
        int cnt = 0;
        #pragma unroll
        for (int c = 0; c < WCHUNKS; c++) {
            const int4 p = v[c];
            const int g = wid * WCHUNKS + c;
            const bool va = ((g | lane) != 0) && is_valid(p.x, p.y);
            const bool vb = is_valid(p.z, p.w);
            bA[c] = __ballot_sync(0xffffffffu, va);
            bB[c] = __ballot_sync(0xffffffffu, vb);
            cntc[c] = cnt;
            cnt += __popc(bA[c]) + __popc(bB[c]);
        }
        if (lane == 0) scnt[wid] = cnt;
        __syncthreads();

        int base = 0;
        #pragma unroll
        for (int w = 0; w < NW; w++) base += (w < wid) ? scnt[w] : 0;
        const int total = scnt[0] + scnt[1] + scnt[2] + scnt[3];

        // ---- Pass 2: scatter into contiguous buffer (stable order) ----
        #pragma unroll
        for (int c = 0; c < WCHUNKS; c++) {
            const int4 p = v[c];
            const int fa = (bA[c] >> lane) & 1;
            const int fb = (bB[c] >> lane) & 1;
            const int pos = base + cntc[c] + __popc(bA[c] & lt) + __popc(bB[c] & lt);
            if (fa) buf[pos]      = (p.y << 16) | p.x;
            if (fb) buf[pos + fa] = (p.w << 16) | p.z;
        }
        __syncthreads();

        // ---- Windowed min sq-distance (integer), one sqrt per element ----
        float vsum = 0.0f;
        for (int i = WINDOW_SIZE + t; i < total; i += NTHREADS) {
            const int pki = buf[i];
            const int xi = pki & 0xffff;
            const int yi = pki >> 16;
            int msq = 0x7fffffff;
            #pragma unroll
            for (int j = 1; j <= WINDOW_SIZE; j++) {
                const int pkj = buf[i - j];
                const int dx = xi - (pkj & 0xffff);
                const int dy = yi - (pkj >> 16);
                msq = min(msq, dx * dx + dy * dy);
            }
            vsum += fmaxf(sqrtf((float)msq) - MAX_REACH, 0.0f);
        }

        #pragma unroll
        for (int o = 16; o > 0; o >>= 1)
            vsum += __shfl_xor_sync(0xffffffffu, vsum, o);
        if (lane == 0) partial[wid] = vsum;
        __syncthreads();

        if (t == 0 && total >= WINDOW_SIZE + 1) {
            const float pen = partial[0] + partial[1] + partial[2] + partial[3];
            acc += (double)(pen / (float)(total - WINDOW_SIZE));
            nvs += 1;
        }
        __syncthreads();   // buf/scnt/partial reuse next row

        #pragma unroll
        for (int c = 0; c < WCHUNKS; c++) v[c] = vn[c];
    }

    // One atomic pair per CTA; last CTA finalizes + resets.
    if (t == 0) {
        if (nvs) {
            atomicAdd(&g_total, acc);
            atomicAdd(&g_nvs, nvs);
        }
        __threadfence();
        const unsigned ticket = atomicAdd(&g_counter, 1u);
        if (ticket == (unsigned)(n_ctas - 1)) {
            const double tot = *((volatile double*)&g_total);
            const int    tn  = *((volatile int*)&g_nvs);
            out[0] = (tn > 0) ? (float)(PENALTY_SCALE * tot / (double)tn) : 0.0f;
            g_total = 0.0;
            g_nvs   = 0;
            __threadfence();
            g_counter = 0u;
        }
    }
}

extern "C" void kernel_launch(void* const* d_in, const int* in_sizes, int n_in,
                              void* d_out, int out_size) {
    const int* in = (const int*)d_in[0];
    const int B = in_sizes[0] / ROW_LEN;            // 2048 rows
    const int n_ctas = B / ROWS_PER_CTA;            // 1024 CTAs — one wave
    reach_loss_wave<<<n_ctas, NTHREADS>>>(in, (float*)d_out, n_ctas);
}